// round 16
// baseline (speedup 1.0000x reference)
#include <cuda_runtime.h>
#include <cuda_fp16.h>
#include <math.h>

// Problem constants
#define B_SZ 4
#define NSEQ 2048
#define CDIM 1024
#define NHEAD 16
#define HD 64
#define MROWS 8192
#define QKVDIM 3072
#define BHTOT 64

// ---------------------------------------------------------------------------
// Static device scratch (allocation-free kernel_launch)
// ---------------------------------------------------------------------------
__device__ __half g_qkv16[MROWS * QKVDIM];        // fp16 qkv intermediate
__device__ __half g_x16[MROWS * CDIM];            // x single fp16
__device__ __half g_att16[MROWS * CDIM];          // att single fp16
__device__ __half g_wqkv16[QKVDIM * CDIM];        // w_qkv single fp16
__device__ __half g_wproj16[CDIM * CDIM];         // w_proj single fp16
__device__ __half g_qh[BHTOT * NSEQ * HD];        // fp16 Q (pre-scaled 1/8)
__device__ __half g_kh[BHTOT * NSEQ * HD];        // fp16 K
__device__ __half g_vh[BHTOT * NSEQ * HD];        // fp16 V

// ---------------------------------------------------------------------------
// Helpers
// ---------------------------------------------------------------------------
__device__ __forceinline__ unsigned smem_u32(const void* p) {
    unsigned a;
    asm("{ .reg .u64 t; cvta.to.shared.u64 t, %1; cvt.u32.u64 %0, t; }"
        : "=r"(a) : "l"(p));
    return a;
}

__device__ __forceinline__ void ldsm4(unsigned* r, unsigned a) {
    asm volatile("ldmatrix.sync.aligned.m8n8.x4.shared.b16 {%0,%1,%2,%3}, [%4];"
        : "=r"(r[0]), "=r"(r[1]), "=r"(r[2]), "=r"(r[3]) : "r"(a));
}
__device__ __forceinline__ void ldsm4t(unsigned* r, unsigned a) {
    asm volatile("ldmatrix.sync.aligned.m8n8.x4.trans.shared.b16 {%0,%1,%2,%3}, [%4];"
        : "=r"(r[0]), "=r"(r[1]), "=r"(r[2]), "=r"(r[3]) : "r"(a));
}
// fp16 HMMA
__device__ __forceinline__ void mma16816h(float* d, const unsigned* a,
                                          unsigned b0, unsigned b1) {
    asm volatile(
        "mma.sync.aligned.m16n8k16.row.col.f32.f16.f16.f32 "
        "{%0,%1,%2,%3}, {%4,%5,%6,%7}, {%8,%9}, {%0,%1,%2,%3};"
        : "+f"(d[0]), "+f"(d[1]), "+f"(d[2]), "+f"(d[3])
        : "r"(a[0]), "r"(a[1]), "r"(a[2]), "r"(a[3]), "r"(b0), "r"(b1));
}

#define CP16(sa, g) \
    asm volatile("cp.async.cg.shared.global [%0], [%1], 16;" :: "r"(sa), "l"(g))
#define CP_COMMIT() asm volatile("cp.async.commit_group;")
#define CP_WAIT1()  asm volatile("cp.async.wait_group 1;")
#define CP_WAIT0()  asm volatile("cp.async.wait_group 0;")

// chunk swizzle: 128B rows, 8 x 16B chunks
__device__ __forceinline__ unsigned swz(int row, int chunk) {
    return (unsigned)(row * 128 + ((chunk ^ (row & 7)) * 16));
}

// exp(x) * 2^-8 via MUFU: 1 FFMA + 1 MUFU.EX2 (separate pipe from FMA).
__device__ __forceinline__ float exp_p8(float x) {
    float e;
    float a = fmaf(x, 1.442695041f, -8.0f);
    asm("ex2.approx.f32 %0, %1;" : "=f"(e) : "f"(a));
    return e;
}

__device__ __forceinline__ unsigned pack_h2(float x, float y) {
    __half2 h = __floats2half2_rn(x, y);
    return *reinterpret_cast<unsigned*>(&h);
}

// ---------------------------------------------------------------------------
// One merged split kernel: x, w_qkv, w_proj -> single fp16
// ---------------------------------------------------------------------------
#define NX4 (MROWS * CDIM / 4)
#define NQ4 (QKVDIM * CDIM / 4)
#define NP4 (CDIM * CDIM / 4)

__global__ __launch_bounds__(256) void split_all(
    const float* __restrict__ x, const float* __restrict__ wq,
    const float* __restrict__ wp,
    __half* __restrict__ x16, __half* __restrict__ wq16,
    __half* __restrict__ wp16)
{
    int i = blockIdx.x * 256 + threadIdx.x;
    const float* src;
    __half* dst;
    if (i < NX4)            { src = x;  dst = x16; }
    else if (i < NX4 + NQ4) { i -= NX4; src = wq; dst = wq16; }
    else                    { i -= NX4 + NQ4; src = wp; dst = wp16; }
    float4 v = reinterpret_cast<const float4*>(src)[i];
    reinterpret_cast<unsigned*>(dst)[2 * i]     = pack_h2(v.x, v.y);
    reinterpret_cast<unsigned*>(dst)[2 * i + 1] = pack_h2(v.z, v.w);
}

// ---------------------------------------------------------------------------
// fp16 HMMA GEMM (NT): C[m,n] = sum_k A[m,k]*B[n,k] (+bias). Single-pass.
// 128(M) x 256(N) tile, 512 threads (16 warps: 2 m-halves x 8 n-groups).
// BK=64 stage {A 16K | B 32K} = 48KB x 3 stages.
// HALFOUT: store fp16 (half2 packs); else fp32.
// ---------------------------------------------------------------------------
#define GS_STAGE 49152
#define GEMM_SMEM (3 * GS_STAGE)     // 147456
#define NSTAGES 16                   // K=1024 / 64

template <bool BIAS, bool HALFOUT>
__global__ __launch_bounds__(512) void gemm_hmma(
    const __half* __restrict__ A, const __half* __restrict__ B,
    const float* __restrict__ bias, void* __restrict__ Cv, int N)
{
    extern __shared__ __align__(128) char smc[];
    const unsigned sb = smem_u32(smc);
    const int t = threadIdx.x, lane = t & 31, wid = t >> 5;
    const int wm = wid & 1, wn = wid >> 1;          // wm 0..1, wn 0..7
    const int m0 = blockIdx.y * 128, n0 = blockIdx.x * 256;
    const int K = 1024;
    const int grp = lane >> 3, ri = lane & 7;

    float acc[4][4][4];
#pragma unroll
    for (int a = 0; a < 4; a++)
#pragma unroll
        for (int b = 0; b < 4; b++)
#pragma unroll
            for (int c = 0; c < 4; c++) acc[a][b][c] = 0.f;

    const __half* Ab = A + (size_t)m0 * K;
    const __half* Bb = B + (size_t)n0 * K;

    auto issue = [&](int s, int buf) {
        const int k0 = s * 64;
        const unsigned stb = sb + buf * GS_STAGE;
#pragma unroll
        for (int i = 0; i < 2; i++) {               // A: 1024 chunks
            int idx = i * 512 + t;
            int r = idx >> 3, ch = idx & 7;
            CP16(stb + swz(r, ch), Ab + (size_t)r * K + k0 + ch * 8);
        }
#pragma unroll
        for (int i = 0; i < 4; i++) {               // B: 2048 chunks
            int idx = i * 512 + t;
            int r = idx >> 3, ch = idx & 7;
            CP16(stb + 16384 + swz(r, ch), Bb + (size_t)r * K + k0 + ch * 8);
        }
    };

    issue(0, 0); CP_COMMIT();
    issue(1, 1); CP_COMMIT();

    for (int it = 0; it < NSTAGES; it++) {
        if (it == NSTAGES - 1) { CP_WAIT0(); } else { CP_WAIT1(); }
        __syncthreads();
        if (it + 2 < NSTAGES) {
            issue(it + 2, (it + 2) % 3);
            CP_COMMIT();
        }
        const unsigned ab = sb + (it % 3) * GS_STAGE;
        const unsigned bb = ab + 16384;
#pragma unroll
        for (int k4 = 0; k4 < 4; k4++) {
            unsigned af[4][4], bf[2][4];
#pragma unroll
            for (int mt = 0; mt < 4; mt++) {
                int r = wm * 64 + mt * 16 + (grp & 1) * 8 + ri;
                int ch = k4 * 2 + (grp >> 1);
                ldsm4(af[mt], ab + swz(r, ch));
            }
#pragma unroll
            for (int np = 0; np < 2; np++) {
                int r = wn * 32 + np * 16 + ((grp >> 1) & 1) * 8 + ri;
                int ch = k4 * 2 + (grp & 1);
                ldsm4(bf[np], bb + swz(r, ch));
            }
#pragma unroll
            for (int mt = 0; mt < 4; mt++)
#pragma unroll
                for (int np = 0; np < 2; np++) {
                    mma16816h(acc[mt][2 * np],     af[mt], bf[np][0], bf[np][1]);
                    mma16816h(acc[mt][2 * np + 1], af[mt], bf[np][2], bf[np][3]);
                }
        }
    }

    // epilogue
#pragma unroll
    for (int mt = 0; mt < 4; mt++)
#pragma unroll
        for (int nt = 0; nt < 4; nt++) {
            int col = n0 + wn * 32 + nt * 8 + (lane & 3) * 2;
            int r0 = m0 + wm * 64 + mt * 16 + (lane >> 2);
            float bx = 0.f, by = 0.f;
            if (BIAS) { bx = bias[col]; by = bias[col + 1]; }
            float a0 = acc[mt][nt][0] + bx, a1 = acc[mt][nt][1] + by;
            float a2 = acc[mt][nt][2] + bx, a3 = acc[mt][nt][3] + by;
            if (HALFOUT) {
                __half* C = (__half*)Cv;
                *reinterpret_cast<unsigned*>(&C[(size_t)r0 * N + col]) =
                    pack_h2(a0, a1);
                *reinterpret_cast<unsigned*>(&C[(size_t)(r0 + 8) * N + col]) =
                    pack_h2(a2, a3);
            } else {
                float* C = (float*)Cv;
                *reinterpret_cast<float2*>(&C[(size_t)r0 * N + col]) =
                    make_float2(a0, a1);
                *reinterpret_cast<float2*>(&C[(size_t)(r0 + 8) * N + col]) =
                    make_float2(a2, a3);
            }
        }
}

// ---------------------------------------------------------------------------
// Prep: read fp16 qkv, RMSNorm(q,k), RoPE(q,k); emit fp16 Q (pre-scaled 1/8),
// fp16 K, fp16 V in [b*H+h][n][64] layout. Warp per (b,n,h).
// ---------------------------------------------------------------------------
__global__ __launch_bounds__(256) void prep_kernel(
    const __half* __restrict__ qkv,
    const float* __restrict__ cosb, const float* __restrict__ sinb,
    const float* __restrict__ qw, const float* __restrict__ kw,
    __half* __restrict__ Qh, __half* __restrict__ Kh,
    __half* __restrict__ Vh)
{
    const int bn = blockIdx.x;
    const int h = (blockIdx.y << 3) | (threadIdx.x >> 5);
    const int l = threadIdx.x & 31;
    const int b = bn >> 11;
    const int n = bn & 2047;

    const __half* base = qkv + (size_t)bn * QKVDIM + h * HD;
    float q1 = __half2float(base[l]);
    float q2 = __half2float(base[l + 32]);
    float k1 = __half2float(base[CDIM + l]);
    float k2 = __half2float(base[CDIM + l + 32]);
    float v1 = __half2float(base[2 * CDIM + l]);
    float v2 = __half2float(base[2 * CDIM + l + 32]);

    float sq = q1 * q1 + q2 * q2;
    float sk = k1 * k1 + k2 * k2;
#pragma unroll
    for (int o = 16; o > 0; o >>= 1) {
        sq += __shfl_xor_sync(0xffffffffu, sq, o);
        sk += __shfl_xor_sync(0xffffffffu, sk, o);
    }
    float rq = rsqrtf(sq * (1.f / 64.f) + 1e-6f);
    float rk = rsqrtf(sk * (1.f / 64.f) + 1e-6f);
    q1 *= rq * qw[l]; q2 *= rq * qw[l + 32];
    k1 *= rk * kw[l]; k2 *= rk * kw[l + 32];

    float c1 = cosb[n * HD + l], c2 = cosb[n * HD + l + 32];
    float s1 = sinb[n * HD + l], s2 = sinb[n * HD + l + 32];

    size_t o = (((size_t)(b * NHEAD + h)) * NSEQ + n) * HD;
    Qh[o + l]      = __float2half_rn((q1 * c1 - q2 * s1) * 0.125f);
    Qh[o + l + 32] = __float2half_rn((q2 * c2 + q1 * s2) * 0.125f);
    Kh[o + l]      = __float2half_rn(k1 * c1 - k2 * s1);
    Kh[o + l + 32] = __float2half_rn(k2 * c2 + k1 * s2);
    Vh[o + l]      = __float2half_rn(v1);
    Vh[o + l + 32] = __float2half_rn(v2);
}

// ---------------------------------------------------------------------------
// Flash attention on fp16 HMMA, PERSISTENT CTAs (grid 304, 2/SM).
// Each CTA loops over tiles (bh = tile & 63, qt = tile >> 6) so concurrent
// tiles share KV in L2. 256 threads, 128 q rows, KV tiles of 128.
// Fused per-ct: S MMAs -> exp (MUFU) -> l-MMA -> PV.
// NO online max (|s| <= 16); P = exp(s)*2^-8; out = o/l, single fp16.
// SMEM: Q 16K | stage{Kh 16K,Vh 16K}x2 = 64K | ones 512B -> 2 CTAs/SM.
// ---------------------------------------------------------------------------
#define FA_STAGE 32768
#define FA_SMEM (16384 + 2 * FA_STAGE + 512)   // 82432
#define FA_TILES (BHTOT * (NSEQ / 128))        // 1024
#define FA_GRID 304

__global__ __launch_bounds__(256, 2) void flash_hmma(
    const __half* __restrict__ Qh, const __half* __restrict__ Kh,
    const __half* __restrict__ Vh, __half* __restrict__ Att)
{
    extern __shared__ __align__(128) char smc[];
    const unsigned sb = smem_u32(smc);
    const unsigned ob = sb + 16384 + 2 * FA_STAGE;   // ones tile (512B)
    const int t = threadIdx.x, lane = t & 31, w = t >> 5;
    const int grp = lane >> 3, ri = lane & 7;

    // ones tile init (once)
    if (t < 128)
        *reinterpret_cast<unsigned*>(smc + (16384 + 2 * FA_STAGE) + t * 4)
            = 0x3C003C00u;   // half2(1, 1)
    __syncthreads();
    unsigned of[4];
    ldsm4t(of, ob + (lane & 15) * 32);

    for (int tile = blockIdx.x; tile < FA_TILES; tile += FA_GRID) {
        const int bh = tile & 63, qt = tile >> 6;
        const int b = bh >> 4, h = bh & 15;
        const size_t qoff = ((size_t)bh * NSEQ + qt * 128) * HD;
        const size_t kvoff = (size_t)bh * NSEQ * HD;

        auto issue = [&](int j, int s) {
            const unsigned stb = sb + 16384 + s * FA_STAGE;
            const __half* gk = Kh + kvoff + (size_t)(j * 128) * HD;
            const __half* gv = Vh + kvoff + (size_t)(j * 128) * HD;
#pragma unroll
            for (int i = 0; i < 4; i++) {
                int idx = i * 256 + t;
                int r = idx >> 3, ch = idx & 7;
                CP16(stb + swz(r, ch), gk + (size_t)r * HD + ch * 8);
                CP16(stb + 16384 + swz(r, ch), gv + (size_t)r * HD + ch * 8);
            }
        };

        issue(0, 0);
        CP_COMMIT();

        // Q tile -> smem (swizzled); prior-tile Q frags are register-resident
#pragma unroll
        for (int i = 0; i < 4; i++) {
            int idx = i * 256 + t;
            int r = idx >> 3, ch = idx & 7;
            *reinterpret_cast<uint4*>(smc + swz(r, ch)) =
                *reinterpret_cast<const uint4*>(
                    Qh + qoff + (size_t)r * HD + ch * 8);
        }
        __syncthreads();

        unsigned qf[4][4];
#pragma unroll
        for (int kt = 0; kt < 4; kt++) {
            int r = w * 16 + (grp & 1) * 8 + ri;
            int ch = kt * 2 + (grp >> 1);
            ldsm4(qf[kt], sb + swz(r, ch));
        }

        float o[8][4], o9[4];
#pragma unroll
        for (int d = 0; d < 8; d++)
#pragma unroll
            for (int c = 0; c < 4; c++) o[d][c] = 0.f;
#pragma unroll
        for (int c = 0; c < 4; c++) o9[c] = 0.f;

        for (int j = 0; j < NSEQ / 128; j++) {
            CP_WAIT0();
            __syncthreads();
            if (j + 1 < NSEQ / 128) {
                issue(j + 1, (j + 1) & 1);
                CP_COMMIT();
            }
            const unsigned stb = sb + 16384 + (j & 1) * FA_STAGE;

            // fused per-ct: S (16 kv rows) -> exp (MUFU) -> l-MMA -> PV
#pragma unroll
            for (int ct = 0; ct < 8; ct++) {
                float s2[2][4];
#pragma unroll
                for (int c = 0; c < 4; c++) { s2[0][c] = 0.f; s2[1][c] = 0.f; }
#pragma unroll
                for (int kt = 0; kt < 4; kt++) {
                    int r = ct * 16 + ((grp >> 1) & 1) * 8 + ri;
                    int ch = kt * 2 + (grp & 1);
                    unsigned kf[4];
                    ldsm4(kf, stb + swz(r, ch));
                    mma16816h(s2[0], qf[kt], kf[0], kf[1]);
                    mma16816h(s2[1], qf[kt], kf[2], kf[3]);
                }
                unsigned ph[4];
                ph[0] = pack_h2(exp_p8(s2[0][0]), exp_p8(s2[0][1]));
                ph[1] = pack_h2(exp_p8(s2[0][2]), exp_p8(s2[0][3]));
                ph[2] = pack_h2(exp_p8(s2[1][0]), exp_p8(s2[1][1]));
                ph[3] = pack_h2(exp_p8(s2[1][2]), exp_p8(s2[1][3]));
                mma16816h(o9, ph, of[0], of[1]);   // row sums -> l
#pragma unroll
                for (int dp = 0; dp < 4; dp++) {
                    int r = ct * 16 + (lane & 15);
                    int ch = dp * 2 + (lane >> 4);
                    unsigned vf[4];
                    ldsm4t(vf, stb + 16384 + swz(r, ch));
                    mma16816h(o[2 * dp],     ph, vf[0], vf[1]);
                    mma16816h(o[2 * dp + 1], ph, vf[2], vf[3]);
                }
            }
        }

        // epilogue: o/l (2^-8 cancels) -> single fp16 att [B,N,C]
        const float inv0 = 1.0f / o9[0], inv1 = 1.0f / o9[2];
#pragma unroll
        for (int dt = 0; dt < 8; dt++) {
            int col = h * 64 + dt * 8 + (lane & 3) * 2;
            int r0 = qt * 128 + w * 16 + (lane >> 2);
            size_t i0 = ((size_t)b * NSEQ + r0) * CDIM + col;
            size_t i1 = ((size_t)b * NSEQ + r0 + 8) * CDIM + col;
            *reinterpret_cast<unsigned*>(&Att[i0]) =
                pack_h2(o[dt][0] * inv0, o[dt][1] * inv0);
            *reinterpret_cast<unsigned*>(&Att[i1]) =
                pack_h2(o[dt][2] * inv1, o[dt][3] * inv1);
        }
    }
}

// ---------------------------------------------------------------------------
extern "C" void kernel_launch(void* const* d_in, const int* in_sizes, int n_in,
                              void* d_out, int out_size)
{
    const float* x      = (const float*)d_in[0];
    const float* cosb   = (const float*)d_in[1];
    const float* sinb   = (const float*)d_in[2];
    const float* w_qkv  = (const float*)d_in[3];
    const float* w_proj = (const float*)d_in[4];
    const float* b_proj = (const float*)d_in[5];
    const float* qw     = (const float*)d_in[6];
    const float* kw     = (const float*)d_in[7];
    float* out = (float*)d_out;

    __half *qkv16, *x16, *att16, *wq16, *wp16;
    __half *qh, *kh, *vh;
    cudaGetSymbolAddress((void**)&qkv16, g_qkv16);
    cudaGetSymbolAddress((void**)&x16, g_x16);
    cudaGetSymbolAddress((void**)&att16, g_att16);
    cudaGetSymbolAddress((void**)&wq16, g_wqkv16);
    cudaGetSymbolAddress((void**)&wp16, g_wproj16);
    cudaGetSymbolAddress((void**)&qh, g_qh);
    cudaGetSymbolAddress((void**)&kh, g_kh);
    cudaGetSymbolAddress((void**)&vh, g_vh);

    cudaFuncSetAttribute((const void*)gemm_hmma<false, true>,
                         cudaFuncAttributeMaxDynamicSharedMemorySize, GEMM_SMEM);
    cudaFuncSetAttribute((const void*)gemm_hmma<true, false>,
                         cudaFuncAttributeMaxDynamicSharedMemorySize, GEMM_SMEM);
    cudaFuncSetAttribute(flash_hmma,
                         cudaFuncAttributeMaxDynamicSharedMemorySize, FA_SMEM);

    // 0) splits: x, w_qkv, w_proj -> single fp16 (one launch)
    split_all<<<(NX4 + NQ4 + NP4) / 256, 256>>>(
        x, w_qkv, w_proj, x16, wq16, wp16);

    // 1) qkv = x @ w_qkv^T (fp16 in, fp16 out), 128x256 tiles
    gemm_hmma<false, true><<<dim3(QKVDIM / 256, MROWS / 128), 512, GEMM_SMEM>>>(
        x16, wq16, nullptr, qkv16, QKVDIM);

    // 2) rmsnorm + rope -> fp16 Q(pre-scaled), K, V
    prep_kernel<<<dim3(MROWS, 2), 256>>>(qkv16, cosb, sinb, qw, kw, qh, kh, vh);

    // 3) flash attention -> att single fp16 (persistent)
    flash_hmma<<<FA_GRID, 256, FA_SMEM>>>(qh, kh, vh, att16);

    // 4) out = att @ w_proj^T + b (fp16 in, fp32 out), 128x256 tiles
    gemm_hmma<true, false><<<dim3(CDIM / 256, MROWS / 128), 512, GEMM_SMEM>>>(
        att16, wp16, b_proj, out, CDIM);
}

// round 17
// speedup vs baseline: 1.0013x; 1.0013x over previous
#include <cuda_runtime.h>
#include <cuda_fp16.h>
#include <math.h>

// Problem constants
#define B_SZ 4
#define NSEQ 2048
#define CDIM 1024
#define NHEAD 16
#define HD 64
#define MROWS 8192
#define QKVDIM 3072
#define BHTOT 64

// ---------------------------------------------------------------------------
// Static device scratch (allocation-free kernel_launch)
// ---------------------------------------------------------------------------
__device__ __half g_qkv16[MROWS * QKVDIM];        // fp16 qkv intermediate
__device__ __half g_x16[MROWS * CDIM];            // x single fp16
__device__ __half g_att16[MROWS * CDIM];          // att single fp16
__device__ __half g_wqkv16[QKVDIM * CDIM];        // w_qkv single fp16
__device__ __half g_wproj16[CDIM * CDIM];         // w_proj single fp16
__device__ __half g_qh[BHTOT * NSEQ * HD];        // fp16 Q (pre-scaled 1/8)
__device__ __half g_kh[BHTOT * NSEQ * HD];        // fp16 K
__device__ __half g_vh[BHTOT * NSEQ * HD];        // fp16 V

// ---------------------------------------------------------------------------
// Helpers
// ---------------------------------------------------------------------------
__device__ __forceinline__ unsigned smem_u32(const void* p) {
    unsigned a;
    asm("{ .reg .u64 t; cvta.to.shared.u64 t, %1; cvt.u32.u64 %0, t; }"
        : "=r"(a) : "l"(p));
    return a;
}

__device__ __forceinline__ void ldsm4(unsigned* r, unsigned a) {
    asm volatile("ldmatrix.sync.aligned.m8n8.x4.shared.b16 {%0,%1,%2,%3}, [%4];"
        : "=r"(r[0]), "=r"(r[1]), "=r"(r[2]), "=r"(r[3]) : "r"(a));
}
__device__ __forceinline__ void ldsm4t(unsigned* r, unsigned a) {
    asm volatile("ldmatrix.sync.aligned.m8n8.x4.trans.shared.b16 {%0,%1,%2,%3}, [%4];"
        : "=r"(r[0]), "=r"(r[1]), "=r"(r[2]), "=r"(r[3]) : "r"(a));
}
// fp16 HMMA
__device__ __forceinline__ void mma16816h(float* d, const unsigned* a,
                                          unsigned b0, unsigned b1) {
    asm volatile(
        "mma.sync.aligned.m16n8k16.row.col.f32.f16.f16.f32 "
        "{%0,%1,%2,%3}, {%4,%5,%6,%7}, {%8,%9}, {%0,%1,%2,%3};"
        : "+f"(d[0]), "+f"(d[1]), "+f"(d[2]), "+f"(d[3])
        : "r"(a[0]), "r"(a[1]), "r"(a[2]), "r"(a[3]), "r"(b0), "r"(b1));
}

#define CP16(sa, g) \
    asm volatile("cp.async.cg.shared.global [%0], [%1], 16;" :: "r"(sa), "l"(g))
#define CP_COMMIT() asm volatile("cp.async.commit_group;")
#define CP_WAIT1()  asm volatile("cp.async.wait_group 1;")
#define CP_WAIT0()  asm volatile("cp.async.wait_group 0;")

// chunk swizzle: 128B rows, 8 x 16B chunks
__device__ __forceinline__ unsigned swz(int row, int chunk) {
    return (unsigned)(row * 128 + ((chunk ^ (row & 7)) * 16));
}

// exp(x) * 2^-8 via MUFU: 1 FFMA + 1 MUFU.EX2 (separate pipe from FMA).
__device__ __forceinline__ float exp_p8(float x) {
    float e;
    float a = fmaf(x, 1.442695041f, -8.0f);
    asm("ex2.approx.f32 %0, %1;" : "=f"(e) : "f"(a));
    return e;
}

__device__ __forceinline__ unsigned pack_h2(float x, float y) {
    __half2 h = __floats2half2_rn(x, y);
    return *reinterpret_cast<unsigned*>(&h);
}

// ---------------------------------------------------------------------------
// One merged split kernel: x, w_qkv, w_proj -> single fp16
// ---------------------------------------------------------------------------
#define NX4 (MROWS * CDIM / 4)
#define NQ4 (QKVDIM * CDIM / 4)
#define NP4 (CDIM * CDIM / 4)

__global__ __launch_bounds__(256) void split_all(
    const float* __restrict__ x, const float* __restrict__ wq,
    const float* __restrict__ wp,
    __half* __restrict__ x16, __half* __restrict__ wq16,
    __half* __restrict__ wp16)
{
    int i = blockIdx.x * 256 + threadIdx.x;
    const float* src;
    __half* dst;
    if (i < NX4)            { src = x;  dst = x16; }
    else if (i < NX4 + NQ4) { i -= NX4; src = wq; dst = wq16; }
    else                    { i -= NX4 + NQ4; src = wp; dst = wp16; }
    float4 v = reinterpret_cast<const float4*>(src)[i];
    reinterpret_cast<unsigned*>(dst)[2 * i]     = pack_h2(v.x, v.y);
    reinterpret_cast<unsigned*>(dst)[2 * i + 1] = pack_h2(v.z, v.w);
}

// ---------------------------------------------------------------------------
// fp16 HMMA GEMM (NT): C[m,n] = sum_k A[m,k]*B[n,k] (+bias). Single-pass.
// 128(M) x 256(N) tile, 512 threads (16 warps: 2 m-halves x 8 n-groups).
// BK=64 stage {A 16K | B 32K} = 48KB x 3 stages.
// HALFOUT: store fp16 (half2 packs); else fp32.
// ---------------------------------------------------------------------------
#define GS_STAGE 49152
#define GEMM_SMEM (3 * GS_STAGE)     // 147456
#define NSTAGES 16                   // K=1024 / 64

template <bool BIAS, bool HALFOUT>
__global__ __launch_bounds__(512) void gemm_hmma(
    const __half* __restrict__ A, const __half* __restrict__ B,
    const float* __restrict__ bias, void* __restrict__ Cv, int N)
{
    extern __shared__ __align__(128) char smc[];
    const unsigned sb = smem_u32(smc);
    const int t = threadIdx.x, lane = t & 31, wid = t >> 5;
    const int wm = wid & 1, wn = wid >> 1;          // wm 0..1, wn 0..7
    const int m0 = blockIdx.y * 128, n0 = blockIdx.x * 256;
    const int K = 1024;
    const int grp = lane >> 3, ri = lane & 7;

    float acc[4][4][4];
#pragma unroll
    for (int a = 0; a < 4; a++)
#pragma unroll
        for (int b = 0; b < 4; b++)
#pragma unroll
            for (int c = 0; c < 4; c++) acc[a][b][c] = 0.f;

    const __half* Ab = A + (size_t)m0 * K;
    const __half* Bb = B + (size_t)n0 * K;

    auto issue = [&](int s, int buf) {
        const int k0 = s * 64;
        const unsigned stb = sb + buf * GS_STAGE;
#pragma unroll
        for (int i = 0; i < 2; i++) {               // A: 1024 chunks
            int idx = i * 512 + t;
            int r = idx >> 3, ch = idx & 7;
            CP16(stb + swz(r, ch), Ab + (size_t)r * K + k0 + ch * 8);
        }
#pragma unroll
        for (int i = 0; i < 4; i++) {               // B: 2048 chunks
            int idx = i * 512 + t;
            int r = idx >> 3, ch = idx & 7;
            CP16(stb + 16384 + swz(r, ch), Bb + (size_t)r * K + k0 + ch * 8);
        }
    };

    issue(0, 0); CP_COMMIT();
    issue(1, 1); CP_COMMIT();

    for (int it = 0; it < NSTAGES; it++) {
        if (it == NSTAGES - 1) { CP_WAIT0(); } else { CP_WAIT1(); }
        __syncthreads();
        if (it + 2 < NSTAGES) {
            issue(it + 2, (it + 2) % 3);
            CP_COMMIT();
        }
        const unsigned ab = sb + (it % 3) * GS_STAGE;
        const unsigned bb = ab + 16384;
#pragma unroll
        for (int k4 = 0; k4 < 4; k4++) {
            unsigned af[4][4], bf[2][4];
#pragma unroll
            for (int mt = 0; mt < 4; mt++) {
                int r = wm * 64 + mt * 16 + (grp & 1) * 8 + ri;
                int ch = k4 * 2 + (grp >> 1);
                ldsm4(af[mt], ab + swz(r, ch));
            }
#pragma unroll
            for (int np = 0; np < 2; np++) {
                int r = wn * 32 + np * 16 + ((grp >> 1) & 1) * 8 + ri;
                int ch = k4 * 2 + (grp & 1);
                ldsm4(bf[np], bb + swz(r, ch));
            }
#pragma unroll
            for (int mt = 0; mt < 4; mt++)
#pragma unroll
                for (int np = 0; np < 2; np++) {
                    mma16816h(acc[mt][2 * np],     af[mt], bf[np][0], bf[np][1]);
                    mma16816h(acc[mt][2 * np + 1], af[mt], bf[np][2], bf[np][3]);
                }
        }
    }

    // epilogue
#pragma unroll
    for (int mt = 0; mt < 4; mt++)
#pragma unroll
        for (int nt = 0; nt < 4; nt++) {
            int col = n0 + wn * 32 + nt * 8 + (lane & 3) * 2;
            int r0 = m0 + wm * 64 + mt * 16 + (lane >> 2);
            float bx = 0.f, by = 0.f;
            if (BIAS) { bx = bias[col]; by = bias[col + 1]; }
            float a0 = acc[mt][nt][0] + bx, a1 = acc[mt][nt][1] + by;
            float a2 = acc[mt][nt][2] + bx, a3 = acc[mt][nt][3] + by;
            if (HALFOUT) {
                __half* C = (__half*)Cv;
                *reinterpret_cast<unsigned*>(&C[(size_t)r0 * N + col]) =
                    pack_h2(a0, a1);
                *reinterpret_cast<unsigned*>(&C[(size_t)(r0 + 8) * N + col]) =
                    pack_h2(a2, a3);
            } else {
                float* C = (float*)Cv;
                *reinterpret_cast<float2*>(&C[(size_t)r0 * N + col]) =
                    make_float2(a0, a1);
                *reinterpret_cast<float2*>(&C[(size_t)(r0 + 8) * N + col]) =
                    make_float2(a2, a3);
            }
        }
}

// ---------------------------------------------------------------------------
// Prep: read fp16 qkv, RMSNorm(q,k), RoPE(q,k); emit fp16 Q (pre-scaled 1/8),
// fp16 K, fp16 V in [b*H+h][n][64] layout. Warp per (b,n,h).
// ---------------------------------------------------------------------------
__global__ __launch_bounds__(256) void prep_kernel(
    const __half* __restrict__ qkv,
    const float* __restrict__ cosb, const float* __restrict__ sinb,
    const float* __restrict__ qw, const float* __restrict__ kw,
    __half* __restrict__ Qh, __half* __restrict__ Kh,
    __half* __restrict__ Vh)
{
    const int bn = blockIdx.x;
    const int h = (blockIdx.y << 3) | (threadIdx.x >> 5);
    const int l = threadIdx.x & 31;
    const int b = bn >> 11;
    const int n = bn & 2047;

    const __half* base = qkv + (size_t)bn * QKVDIM + h * HD;
    float q1 = __half2float(base[l]);
    float q2 = __half2float(base[l + 32]);
    float k1 = __half2float(base[CDIM + l]);
    float k2 = __half2float(base[CDIM + l + 32]);
    float v1 = __half2float(base[2 * CDIM + l]);
    float v2 = __half2float(base[2 * CDIM + l + 32]);

    float sq = q1 * q1 + q2 * q2;
    float sk = k1 * k1 + k2 * k2;
#pragma unroll
    for (int o = 16; o > 0; o >>= 1) {
        sq += __shfl_xor_sync(0xffffffffu, sq, o);
        sk += __shfl_xor_sync(0xffffffffu, sk, o);
    }
    float rq = rsqrtf(sq * (1.f / 64.f) + 1e-6f);
    float rk = rsqrtf(sk * (1.f / 64.f) + 1e-6f);
    q1 *= rq * qw[l]; q2 *= rq * qw[l + 32];
    k1 *= rk * kw[l]; k2 *= rk * kw[l + 32];

    float c1 = cosb[n * HD + l], c2 = cosb[n * HD + l + 32];
    float s1 = sinb[n * HD + l], s2 = sinb[n * HD + l + 32];

    size_t o = (((size_t)(b * NHEAD + h)) * NSEQ + n) * HD;
    Qh[o + l]      = __float2half_rn((q1 * c1 - q2 * s1) * 0.125f);
    Qh[o + l + 32] = __float2half_rn((q2 * c2 + q1 * s2) * 0.125f);
    Kh[o + l]      = __float2half_rn(k1 * c1 - k2 * s1);
    Kh[o + l + 32] = __float2half_rn(k2 * c2 + k1 * s2);
    Vh[o + l]      = __float2half_rn(v1);
    Vh[o + l + 32] = __float2half_rn(v2);
}

// ---------------------------------------------------------------------------
// Flash attention on fp16 HMMA. 256 threads, 128 q rows, KV tiles of 128.
// (Non-persistent grid — R14 config, measured 171us @ tensor 70%.)
// Fused per-ct pipeline: S MMAs (16 kv rows) -> exp (MUFU) -> l-MMA -> PV.
// NO online max (|s| <= 16 bound); P = exp(s)*2^-8 via ex2.approx with
// folded bias; out = o/l (2^-8 cancels), single fp16.
// SMEM: Q 16K | stage{Kh 16K,Vh 16K}x2 = 64K | ones 512B -> 2 CTAs/SM.
// ---------------------------------------------------------------------------
#define FA_STAGE 32768
#define FA_SMEM (16384 + 2 * FA_STAGE + 512)   // 82432

__global__ __launch_bounds__(256, 2) void flash_hmma(
    const __half* __restrict__ Qh, const __half* __restrict__ Kh,
    const __half* __restrict__ Vh, __half* __restrict__ Att)
{
    extern __shared__ __align__(128) char smc[];
    const unsigned sb = smem_u32(smc);
    const unsigned ob = sb + 16384 + 2 * FA_STAGE;   // ones tile (512B)
    const int t = threadIdx.x, lane = t & 31, w = t >> 5;
    const int bh = blockIdx.x, qt = blockIdx.y;
    const int b = bh >> 4, h = bh & 15;
    const int grp = lane >> 3, ri = lane & 7;

    const size_t qoff = ((size_t)bh * NSEQ + qt * 128) * HD;
    const size_t kvoff = (size_t)bh * NSEQ * HD;

    const __half* mats[2] = {Kh, Vh};

    auto issue = [&](int j, int s) {
        const unsigned stb = sb + 16384 + s * FA_STAGE;
#pragma unroll
        for (int m = 0; m < 2; m++) {
            const __half* g = mats[m] + kvoff + (size_t)(j * 128) * HD;
            const unsigned mb = stb + m * 16384;
#pragma unroll
            for (int i = 0; i < 4; i++) {
                int idx = i * 256 + t;
                int r = idx >> 3, ch = idx & 7;
                CP16(mb + swz(r, ch), g + (size_t)r * HD + ch * 8);
            }
        }
    };

    issue(0, 0);
    CP_COMMIT();

    // Q tile -> smem (swizzled); ones tile init
#pragma unroll
    for (int i = 0; i < 4; i++) {
        int idx = i * 256 + t;
        int r = idx >> 3, ch = idx & 7;
        *reinterpret_cast<uint4*>(smc + swz(r, ch)) =
            *reinterpret_cast<const uint4*>(Qh + qoff + (size_t)r * HD + ch * 8);
    }
    if (t < 128)
        *reinterpret_cast<unsigned*>(smc + (16384 + 2 * FA_STAGE) + t * 4)
            = 0x3C003C00u;   // half2(1, 1)
    __syncthreads();

    unsigned qf[4][4];
#pragma unroll
    for (int kt = 0; kt < 4; kt++) {
        int r = w * 16 + (grp & 1) * 8 + ri;
        int ch = kt * 2 + (grp >> 1);
        ldsm4(qf[kt], sb + swz(r, ch));
    }
    // ones B-frag (k16 x n8, all 1.0) — loaded once
    unsigned of[4];
    ldsm4t(of, ob + (lane & 15) * 32);

    float o[8][4], o9[4];
#pragma unroll
    for (int d = 0; d < 8; d++)
#pragma unroll
        for (int c = 0; c < 4; c++) o[d][c] = 0.f;
#pragma unroll
    for (int c = 0; c < 4; c++) o9[c] = 0.f;

    for (int j = 0; j < NSEQ / 128; j++) {
        CP_WAIT0();
        __syncthreads();
        if (j + 1 < NSEQ / 128) {
            issue(j + 1, (j + 1) & 1);
            CP_COMMIT();
        }
        const unsigned stb = sb + 16384 + (j & 1) * FA_STAGE;

        // fused per-ct: S (16 kv rows) -> exp (MUFU) -> l-MMA -> PV
#pragma unroll
        for (int ct = 0; ct < 8; ct++) {
            float s2[2][4];
#pragma unroll
            for (int c = 0; c < 4; c++) { s2[0][c] = 0.f; s2[1][c] = 0.f; }
#pragma unroll
            for (int kt = 0; kt < 4; kt++) {
                int r = ct * 16 + ((grp >> 1) & 1) * 8 + ri;
                int ch = kt * 2 + (grp & 1);
                unsigned kf[4];
                ldsm4(kf, stb + swz(r, ch));
                mma16816h(s2[0], qf[kt], kf[0], kf[1]);
                mma16816h(s2[1], qf[kt], kf[2], kf[3]);
            }
            unsigned ph[4];
            ph[0] = pack_h2(exp_p8(s2[0][0]), exp_p8(s2[0][1]));
            ph[1] = pack_h2(exp_p8(s2[0][2]), exp_p8(s2[0][3]));
            ph[2] = pack_h2(exp_p8(s2[1][0]), exp_p8(s2[1][1]));
            ph[3] = pack_h2(exp_p8(s2[1][2]), exp_p8(s2[1][3]));
            mma16816h(o9, ph, of[0], of[1]);   // row sums -> l
#pragma unroll
            for (int dp = 0; dp < 4; dp++) {
                int r = ct * 16 + (lane & 15);
                int ch = dp * 2 + (lane >> 4);
                unsigned vf[4];
                ldsm4t(vf, stb + 16384 + swz(r, ch));
                mma16816h(o[2 * dp],     ph, vf[0], vf[1]);
                mma16816h(o[2 * dp + 1], ph, vf[2], vf[3]);
            }
        }
    }

    // ---- epilogue: o/l (2^-8 cancels) -> single fp16 att [B,N,C] ----
    const float inv0 = 1.0f / o9[0], inv1 = 1.0f / o9[2];
#pragma unroll
    for (int dt = 0; dt < 8; dt++) {
        int col = h * 64 + dt * 8 + (lane & 3) * 2;
        int r0 = qt * 128 + w * 16 + (lane >> 2);
        size_t i0 = ((size_t)b * NSEQ + r0) * CDIM + col;
        size_t i1 = ((size_t)b * NSEQ + r0 + 8) * CDIM + col;
        *reinterpret_cast<unsigned*>(&Att[i0]) =
            pack_h2(o[dt][0] * inv0, o[dt][1] * inv0);
        *reinterpret_cast<unsigned*>(&Att[i1]) =
            pack_h2(o[dt][2] * inv1, o[dt][3] * inv1);
    }
}

// ---------------------------------------------------------------------------
extern "C" void kernel_launch(void* const* d_in, const int* in_sizes, int n_in,
                              void* d_out, int out_size)
{
    const float* x      = (const float*)d_in[0];
    const float* cosb   = (const float*)d_in[1];
    const float* sinb   = (const float*)d_in[2];
    const float* w_qkv  = (const float*)d_in[3];
    const float* w_proj = (const float*)d_in[4];
    const float* b_proj = (const float*)d_in[5];
    const float* qw     = (const float*)d_in[6];
    const float* kw     = (const float*)d_in[7];
    float* out = (float*)d_out;

    __half *qkv16, *x16, *att16, *wq16, *wp16;
    __half *qh, *kh, *vh;
    cudaGetSymbolAddress((void**)&qkv16, g_qkv16);
    cudaGetSymbolAddress((void**)&x16, g_x16);
    cudaGetSymbolAddress((void**)&att16, g_att16);
    cudaGetSymbolAddress((void**)&wq16, g_wqkv16);
    cudaGetSymbolAddress((void**)&wp16, g_wproj16);
    cudaGetSymbolAddress((void**)&qh, g_qh);
    cudaGetSymbolAddress((void**)&kh, g_kh);
    cudaGetSymbolAddress((void**)&vh, g_vh);

    cudaFuncSetAttribute((const void*)gemm_hmma<false, true>,
                         cudaFuncAttributeMaxDynamicSharedMemorySize, GEMM_SMEM);
    cudaFuncSetAttribute((const void*)gemm_hmma<true, false>,
                         cudaFuncAttributeMaxDynamicSharedMemorySize, GEMM_SMEM);
    cudaFuncSetAttribute(flash_hmma,
                         cudaFuncAttributeMaxDynamicSharedMemorySize, FA_SMEM);

    // 0) splits: x, w_qkv, w_proj -> single fp16 (one launch)
    split_all<<<(NX4 + NQ4 + NP4) / 256, 256>>>(
        x, w_qkv, w_proj, x16, wq16, wp16);

    // 1) qkv = x @ w_qkv^T (fp16 in, fp16 out), 128x256 tiles
    gemm_hmma<false, true><<<dim3(QKVDIM / 256, MROWS / 128), 512, GEMM_SMEM>>>(
        x16, wq16, nullptr, qkv16, QKVDIM);

    // 2) rmsnorm + rope -> fp16 Q(pre-scaled), K, V
    prep_kernel<<<dim3(MROWS, 2), 256>>>(qkv16, cosb, sinb, qw, kw, qh, kh, vh);

    // 3) flash attention -> att single fp16 (non-persistent)
    flash_hmma<<<dim3(BHTOT, NSEQ / 128), 256, FA_SMEM>>>(qh, kh, vh, att16);

    // 4) out = att @ w_proj^T + b (fp16 in, fp32 out), 128x256 tiles
    gemm_hmma<true, false><<<dim3(CDIM / 256, MROWS / 128), 512, GEMM_SMEM>>>(
        att16, wp16, b_proj, out, CDIM);
}